// round 8
// baseline (speedup 1.0000x reference)
#include <cuda_runtime.h>
#include <math.h>

#define Bb 64
#define Ss 128
#define DMm 1024
#define Hh 16
#define DKk 64
#define Mm (Bb*Ss)          // 8192
#define FQ_EPS 1e-8f

// ---------------- device scratch (no allocations allowed) ----------------
__device__ unsigned g_keys[8];          // 0..2: max(q/k/v in), 3: max(attn_out), 4..7: max|Wq/Wk/Wv/Wo|
__device__ unsigned g_spkeys[Ss];       // p_attn per-key-column max keys
__device__ float g_sq[Ss], g_sk[Ss], g_sv[Ss];   // per-seq-position int8 scales
__device__ float g_q[Bb*Hh*Ss*DKk];
__device__ float g_k[Bb*Hh*Ss*DKk];
__device__ float g_v[Bb*Hh*Ss*DKk];
__device__ float g_p[Bb*Hh*Ss*Ss];      // scores -> p_attn (in place)
__device__ float g_attn[Mm*DMm];        // attention output in [B,S,DM] layout
__device__ unsigned char g_xq[Mm*DMm];  // quantized activations (u8), reused per projection
__device__ signed char   g_wq[DMm*DMm]; // quantized weights (s8), reused per projection

// monotone key for float max via unsigned atomicMax (handles negatives)
__device__ __forceinline__ unsigned fkey(float f) {
    unsigned b = __float_as_uint(f);
    return (b & 0x80000000u) ? ~b : (b | 0x80000000u);
}
__device__ __forceinline__ float funkey(unsigned k) {
    unsigned b = (k & 0x80000000u) ? (k & 0x7fffffffu) : ~k;
    return __uint_as_float(b);
}

__device__ __forceinline__ float blockReduceMax(float v) {
    __shared__ float sm[32];
    #pragma unroll
    for (int o = 16; o > 0; o >>= 1) v = fmaxf(v, __shfl_xor_sync(0xffffffffu, v, o));
    int lane = threadIdx.x & 31, w = threadIdx.x >> 5;
    if (lane == 0) sm[w] = v;
    __syncthreads();
    int nw = (blockDim.x + 31) >> 5;
    v = (threadIdx.x < nw) ? sm[threadIdx.x] : -INFINITY;
    if (w == 0) {
        #pragma unroll
        for (int o = 16; o > 0; o >>= 1) v = fmaxf(v, __shfl_xor_sync(0xffffffffu, v, o));
    }
    return v;  // valid in thread 0
}

// ---------------- mma / ldmatrix helpers ----------------
__device__ __forceinline__ void ldsm_x4(unsigned &r0, unsigned &r1, unsigned &r2, unsigned &r3,
                                        const void* p) {
    unsigned a = (unsigned)__cvta_generic_to_shared(p);
    asm volatile("ldmatrix.sync.aligned.m8n8.x4.shared.b16 {%0,%1,%2,%3}, [%4];"
                 : "=r"(r0), "=r"(r1), "=r"(r2), "=r"(r3) : "r"(a));
}
__device__ __forceinline__ void mma_u8s8(int* c, const unsigned* a, const unsigned* b) {
    asm volatile("mma.sync.aligned.m16n8k32.row.col.s32.u8.s8.s32 "
                 "{%0,%1,%2,%3}, {%4,%5,%6,%7}, {%8,%9}, {%0,%1,%2,%3};"
                 : "+r"(c[0]), "+r"(c[1]), "+r"(c[2]), "+r"(c[3])
                 : "r"(a[0]), "r"(a[1]), "r"(a[2]), "r"(a[3]), "r"(b[0]), "r"(b[1]));
}

// ---------------- kernels ----------------

__global__ void k_init() {
    int t = threadIdx.x;
    if (t < 8) g_keys[t] = 0u;
    if (t < Ss) g_spkeys[t] = 0u;
}

// global max (optionally of |x|) over n4 float4's -> g_keys[slot]; x==nullptr means g_attn
__global__ void k_redmax4(const float4* __restrict__ x, int n4, int slot, int useabs) {
    if (x == nullptr) x = (const float4*)g_attn;
    float m = -INFINITY;
    for (int i = blockIdx.x * blockDim.x + threadIdx.x; i < n4; i += gridDim.x * blockDim.x) {
        float4 v = x[i];
        if (useabs) {
            m = fmaxf(m, fmaxf(fmaxf(fabsf(v.x), fabsf(v.y)), fmaxf(fabsf(v.z), fabsf(v.w))));
        } else {
            m = fmaxf(m, fmaxf(fmaxf(v.x, v.y), fmaxf(v.z, v.w)));
        }
    }
    m = blockReduceMax(m);
    if (threadIdx.x == 0) atomicMax(&g_keys[slot], fkey(m));
}

// quantize activations f32 -> u8 into g_xq (x==nullptr means g_attn)
__global__ void k_quantX(const float4* __restrict__ x, int n4, int slot) {
    if (x == nullptr) x = (const float4*)g_attn;
    float s = fmaxf(funkey(g_keys[slot]), FQ_EPS) / 255.0f;
    uchar4* o = (uchar4*)g_xq;
    for (int i = blockIdx.x * blockDim.x + threadIdx.x; i < n4; i += gridDim.x * blockDim.x) {
        float4 v = x[i];
        uchar4 u;
        u.x = (unsigned char)fminf(fmaxf(rintf(v.x / s), 0.f), 255.f);
        u.y = (unsigned char)fminf(fmaxf(rintf(v.y / s), 0.f), 255.f);
        u.z = (unsigned char)fminf(fmaxf(rintf(v.z / s), 0.f), 255.f);
        u.w = (unsigned char)fminf(fmaxf(rintf(v.w / s), 0.f), 255.f);
        o[i] = u;
    }
}

// quantize weights f32 -> s8 into g_wq
__global__ void k_quantW(const float4* __restrict__ w, int n4, int slot) {
    float s = fmaxf(funkey(g_keys[slot]), FQ_EPS) / 127.0f;
    char4* o = (char4*)g_wq;
    for (int i = blockIdx.x * blockDim.x + threadIdx.x; i < n4; i += gridDim.x * blockDim.x) {
        float4 v = w[i];
        char4 u;
        u.x = (signed char)fminf(fmaxf(rintf(v.x / s), -127.f), 127.f);
        u.y = (signed char)fminf(fmaxf(rintf(v.y / s), -127.f), 127.f);
        u.z = (signed char)fminf(fmaxf(rintf(v.z / s), -127.f), 127.f);
        u.w = (signed char)fminf(fmaxf(rintf(v.w / s), -127.f), 127.f);
        o[i] = u;
    }
}

// int8 tensor-core GEMM: C[m,n] = (sum_d Xq[m,d]*Wq[n,d]) * s_b + round(bias[n]/s_b)*s_b
// block tile 128x128, K-chunk 64; warp tile 32x64 via m16n8k32 u8*s8 mma.
// mode 0/1/2: scatter to g_q/g_k/g_v in [B,H,S,DK]; mode 3: plain [M,DM] to outp
__global__ __launch_bounds__(256, 2) void k_gemm_i8(const float* __restrict__ bias,
                                                    float* __restrict__ outp,
                                                    int slot_in, int slot_w, int mode) {
    __shared__ unsigned char As[128 * 80];
    __shared__ unsigned char Bs[128 * 80];
    int tid = threadIdx.x, lane = tid & 31, w = tid >> 5;
    int wm = w & 3, wn = w >> 2;           // 4 warps in M, 2 in N
    int bm = blockIdx.y * 128, bn = blockIdx.x * 128;
    int r0 = tid >> 2, q4 = tid & 3;

    int acc[2][8][4] = {};

    // ldmatrix lane addressing (computed once)
    int asel = lane >> 3;
    int arow_off = (lane & 7) + (asel & 1) * 8;
    int akb = (lane >> 4) * 16;
    int bcol_off = (lane & 7) + (lane >> 4) * 8;
    int bkb = ((lane >> 3) & 1) * 16;

    for (int k0 = 0; k0 < DMm; k0 += 64) {
        int4 xa = *(const int4*)&g_xq[(bm + r0) * DMm + k0 + q4 * 16];
        int4 xb = *(const int4*)&g_xq[(bm + r0 + 64) * DMm + k0 + q4 * 16];
        int4 wa = *(const int4*)&g_wq[(bn + r0) * DMm + k0 + q4 * 16];
        int4 wb = *(const int4*)&g_wq[(bn + r0 + 64) * DMm + k0 + q4 * 16];
        __syncthreads();
        *(int4*)&As[r0 * 80 + q4 * 16] = xa;
        *(int4*)&As[(r0 + 64) * 80 + q4 * 16] = xb;
        *(int4*)&Bs[r0 * 80 + q4 * 16] = wa;
        *(int4*)&Bs[(r0 + 64) * 80 + q4 * 16] = wb;
        __syncthreads();
        #pragma unroll
        for (int ks = 0; ks < 2; ks++) {
            unsigned a[2][4];
            #pragma unroll
            for (int mi = 0; mi < 2; mi++) {
                int row = wm * 32 + mi * 16 + arow_off;
                ldsm_x4(a[mi][0], a[mi][1], a[mi][2], a[mi][3], &As[row * 80 + ks * 32 + akb]);
            }
            unsigned b[8][2];
            #pragma unroll
            for (int pr = 0; pr < 4; pr++) {
                int col = wn * 64 + pr * 16 + bcol_off;
                unsigned t0, t1, t2, t3;
                ldsm_x4(t0, t1, t2, t3, &Bs[col * 80 + ks * 32 + bkb]);
                b[pr * 2][0] = t0; b[pr * 2][1] = t1;
                b[pr * 2 + 1][0] = t2; b[pr * 2 + 1][1] = t3;
            }
            #pragma unroll
            for (int mi = 0; mi < 2; mi++)
                #pragma unroll
                for (int ni = 0; ni < 8; ni++)
                    mma_u8s8(acc[mi][ni], a[mi], b[ni]);
        }
    }

    float s_in = fmaxf(funkey(g_keys[slot_in]), FQ_EPS) / 255.0f;
    float s_w  = fmaxf(funkey(g_keys[slot_w]),  FQ_EPS) / 127.0f;
    float s_b = s_in * s_w;
    int gid = lane >> 2, tg = lane & 3;
    #pragma unroll
    for (int mi = 0; mi < 2; mi++) {
        #pragma unroll
        for (int half = 0; half < 2; half++) {
            int m = bm + wm * 32 + mi * 16 + gid + half * 8;
            int b_ = m >> 7, s_ = m & 127;
            #pragma unroll
            for (int ni = 0; ni < 8; ni++) {
                #pragma unroll
                for (int cc = 0; cc < 2; cc++) {
                    int n = bn + wn * 64 + ni * 8 + tg * 2 + cc;
                    float bq = rintf(bias[n] / s_b) * s_b;
                    float v = (float)acc[mi][ni][half * 2 + cc] * s_b + bq;
                    if (mode < 3) {
                        float* out = (mode == 0) ? g_q : (mode == 1) ? g_k : g_v;
                        int h = n >> 6, dk = n & 63;
                        out[((b_ * Hh + h) * Ss + s_) * DKk + dk] = v;
                    } else {
                        outp[m * DMm + n] = v;
                    }
                }
            }
        }
    }
}

// per-seq-position abs-max scale over (B,H,DK) for g_q/g_k/g_v (sel 0/1/2)
__global__ void k_rowscale(int sel) {
    const float* t = (sel == 0) ? g_q : (sel == 1) ? g_k : g_v;
    float* outp    = (sel == 0) ? g_sq : (sel == 1) ? g_sk : g_sv;
    int s = blockIdx.x;
    float m = 0.f;
    for (int u = threadIdx.x; u < Bb * Hh * DKk; u += blockDim.x) {
        int bh = u >> 6, dk = u & 63;
        m = fmaxf(m, fabsf(t[bh * Ss * DKk + s * DKk + dk]));
    }
    m = blockReduceMax(m);
    if (threadIdx.x == 0) outp[s] = fmaxf(m, FQ_EPS) / 127.0f;
}

// scores[b,h,i,j] = (fq_s8(q_i; sq[i]) . fq_s8(k_j; sk[j])) / 8, masked -> g_p (raw)
__global__ void k_scores(const int* __restrict__ mask) {
    __shared__ float Xs[16][68];
    __shared__ float Ws[16][68];
    int bh = blockIdx.z;
    int b_ = bh >> 4;
    int bm = blockIdx.y * 64, bn = blockIdx.x * 64;
    const float* Q = g_q + bh * Ss * DKk;
    const float* K = g_k + bh * Ss * DKk;
    int tid = threadIdx.x;
    int tx = tid & 15, ty = tid >> 4;
    int lr = tid >> 2, lc = (tid & 3) * 4;
    float acc[4][4] = {};
    for (int k0 = 0; k0 < DKk; k0 += 16) {
        float4 xa = *(const float4*)&Q[(bm + lr) * DKk + k0 + lc];
        float4 wa = *(const float4*)&K[(bn + lr) * DKk + k0 + lc];
        float sqv = g_sq[bm + lr];
        float skv = g_sk[bn + lr];
        float xv[4] = {xa.x, xa.y, xa.z, xa.w};
        float wv[4] = {wa.x, wa.y, wa.z, wa.w};
        #pragma unroll
        for (int i = 0; i < 4; i++) {
            Xs[lc + i][lr] = fminf(fmaxf(rintf(xv[i] / sqv), -128.f), 127.f) * sqv;
            Ws[lc + i][lr] = fminf(fmaxf(rintf(wv[i] / skv), -128.f), 127.f) * skv;
        }
        __syncthreads();
        #pragma unroll
        for (int kk = 0; kk < 16; kk++) {
            float a[4], b4[4];
            #pragma unroll
            for (int i = 0; i < 4; i++) a[i]  = Xs[kk][ty * 4 + i];
            #pragma unroll
            for (int j = 0; j < 4; j++) b4[j] = Ws[kk][tx * 4 + j];
            #pragma unroll
            for (int i = 0; i < 4; i++)
                #pragma unroll
                for (int j = 0; j < 4; j++) acc[i][j] += a[i] * b4[j];
        }
        __syncthreads();
    }
    #pragma unroll
    for (int i = 0; i < 4; i++) {
        int si = bm + ty * 4 + i;
        #pragma unroll
        for (int j = 0; j < 4; j++) {
            int sj = bn + tx * 4 + j;
            float v = acc[i][j] * 0.125f;
            if (mask[b_ * Ss * Ss + si * Ss + sj] == 0) v = -1e9f;
            g_p[bh * Ss * Ss + si * Ss + sj] = v;
        }
    }
}

// softmax over last axis of g_p, in place; one block per row
__global__ void k_softmax() {
    int row = blockIdx.x;
    float* p = g_p + row * Ss;
    int t = threadIdx.x;
    float v = p[t];
    __shared__ float sm[4], s2[4];
    float m = v;
    #pragma unroll
    for (int o = 16; o > 0; o >>= 1) m = fmaxf(m, __shfl_xor_sync(0xffffffffu, m, o));
    if ((t & 31) == 0) sm[t >> 5] = m;
    __syncthreads();
    m = fmaxf(fmaxf(sm[0], sm[1]), fmaxf(sm[2], sm[3]));
    float e = expf(v - m);
    float ssum = e;
    #pragma unroll
    for (int o = 16; o > 0; o >>= 1) ssum += __shfl_xor_sync(0xffffffffu, ssum, o);
    if ((t & 31) == 0) s2[t >> 5] = ssum;
    __syncthreads();
    ssum = s2[0] + s2[1] + s2[2] + s2[3];
    p[t] = e / ssum;
}

// p_attn per-key-column max over (b,h,i) -> g_spkeys
__global__ void k_spmax() {
    int bh = blockIdx.x;
    int j = threadIdx.x;
    const float* p = g_p + bh * Ss * Ss;
    float m = 0.f;
    for (int i = 0; i < Ss; i++) m = fmaxf(m, p[i * Ss + j]);
    atomicMax(&g_spkeys[j], fkey(m));
}

// x[b,h,i,dk] = sum_j fq_s8(p[i,j]; sp[j]) * fq_s8(v[j,dk]; sv[j]) -> g_attn [B,S,DM]
__global__ void k_attn() {
    __shared__ float Xs[16][68];
    __shared__ float Ws[16][68];
    int bh = blockIdx.z;
    int b_ = bh >> 4, h_ = bh & 15;
    int bm = blockIdx.y * 64;
    const float* P = g_p + bh * Ss * Ss;
    const float* V = g_v + bh * Ss * DKk;
    int tid = threadIdx.x;
    int tx = tid & 15, ty = tid >> 4;
    int lr = tid >> 2, lc = (tid & 3) * 4;   // P loads: 64 rows x 16 cols
    int vr = tid >> 4, vc = (tid & 15) * 4;  // V loads: 16 rows x 64 cols (NN)
    float acc[4][4] = {};
    for (int k0 = 0; k0 < Ss; k0 += 16) {
        float4 xa = *(const float4*)&P[(bm + lr) * Ss + k0 + lc];
        float4 wa = *(const float4*)&V[(k0 + vr) * DKk + vc];
        float svv = g_sv[k0 + vr];
        float xv[4] = {xa.x, xa.y, xa.z, xa.w};
        float wv[4] = {wa.x, wa.y, wa.z, wa.w};
        #pragma unroll
        for (int i = 0; i < 4; i++) {
            float spv = fmaxf(funkey(g_spkeys[k0 + lc + i]), FQ_EPS) / 127.0f;
            Xs[lc + i][lr] = fminf(fmaxf(rintf(xv[i] / spv), -128.f), 127.f) * spv;
            Ws[vr][vc + i] = fminf(fmaxf(rintf(wv[i] / svv), -128.f), 127.f) * svv;
        }
        __syncthreads();
        #pragma unroll
        for (int kk = 0; kk < 16; kk++) {
            float a[4], b4[4];
            #pragma unroll
            for (int i = 0; i < 4; i++) a[i]  = Xs[kk][ty * 4 + i];
            #pragma unroll
            for (int j = 0; j < 4; j++) b4[j] = Ws[kk][tx * 4 + j];
            #pragma unroll
            for (int i = 0; i < 4; i++)
                #pragma unroll
                for (int j = 0; j < 4; j++) acc[i][j] += a[i] * b4[j];
        }
        __syncthreads();
    }
    #pragma unroll
    for (int i = 0; i < 4; i++) {
        int si = bm + ty * 4 + i;   // query position
        #pragma unroll
        for (int j = 0; j < 4; j++) {
            int dk = tx * 4 + j;
            g_attn[(b_ * Ss + si) * DMm + h_ * DKk + dk] = acc[i][j];
        }
    }
}

extern "C" void kernel_launch(void* const* d_in, const int* in_sizes, int n_in,
                              void* d_out, int out_size) {
    const float* query = (const float*)d_in[0];
    const float* key   = (const float*)d_in[1];
    const float* value = (const float*)d_in[2];
    const int*   mask  = (const int*)d_in[3];
    const float* Wq = (const float*)d_in[4];
    const float* bq = (const float*)d_in[5];
    const float* Wk = (const float*)d_in[6];
    const float* bk = (const float*)d_in[7];
    const float* Wv = (const float*)d_in[8];
    const float* bv = (const float*)d_in[9];
    const float* Wo = (const float*)d_in[10];
    const float* bo = (const float*)d_in[11];
    float* out = (float*)d_out;

    const int NX4 = Mm * DMm / 4;   // activation float4 count
    const int NW4 = DMm * DMm / 4;  // weight float4 count

    k_init<<<1, 128>>>();

    // per-tensor scale stats
    k_redmax4<<<1024, 256>>>((const float4*)query, NX4, 0, 0);
    k_redmax4<<<1024, 256>>>((const float4*)key,   NX4, 1, 0);
    k_redmax4<<<1024, 256>>>((const float4*)value, NX4, 2, 0);
    k_redmax4<<<512, 256>>>((const float4*)Wq, NW4, 4, 1);
    k_redmax4<<<512, 256>>>((const float4*)Wk, NW4, 5, 1);
    k_redmax4<<<512, 256>>>((const float4*)Wv, NW4, 6, 1);
    k_redmax4<<<512, 256>>>((const float4*)Wo, NW4, 7, 1);

    // projections: quantize then int8 tensor-core GEMM (sequential buffer reuse)
    dim3 gg(DMm / 128, Mm / 128);
    k_quantX<<<2048, 256>>>((const float4*)query, NX4, 0);
    k_quantW<<<1024, 256>>>((const float4*)Wq, NW4, 4);
    k_gemm_i8<<<gg, 256>>>(bq, nullptr, 0, 4, 0);
    k_quantX<<<2048, 256>>>((const float4*)key, NX4, 1);
    k_quantW<<<1024, 256>>>((const float4*)Wk, NW4, 5);
    k_gemm_i8<<<gg, 256>>>(bk, nullptr, 1, 5, 1);
    k_quantX<<<2048, 256>>>((const float4*)value, NX4, 2);
    k_quantW<<<1024, 256>>>((const float4*)Wv, NW4, 6);
    k_gemm_i8<<<gg, 256>>>(bv, nullptr, 2, 6, 2);

    // per-seq-position scales for q/k/v
    k_rowscale<<<Ss, 256>>>(0);
    k_rowscale<<<Ss, 256>>>(1);
    k_rowscale<<<Ss, 256>>>(2);

    // attention
    k_scores<<<dim3(2, 2, Bb * Hh), 256>>>(mask);
    k_softmax<<<Bb * Hh * Ss, 128>>>();
    k_spmax<<<Bb * Hh, Ss>>>();
    k_attn<<<dim3(1, 2, Bb * Hh), 256>>>();

    // output projection
    k_redmax4<<<1024, 256>>>(nullptr, NX4, 3, 0);
    k_quantX<<<2048, 256>>>(nullptr, NX4, 3);
    k_quantW<<<1024, 256>>>((const float4*)Wo, NW4, 7);
    k_gemm_i8<<<gg, 256>>>(bo, out, 3, 7, 3);
}

// round 9
// speedup vs baseline: 1.1430x; 1.1430x over previous
#include <cuda_runtime.h>
#include <cuda_fp16.h>
#include <math.h>

#define Bb 64
#define Ss 128
#define DMm 1024
#define Hh 16
#define DKk 64
#define Mm (Bb*Ss)          // 8192
#define FQ_EPS 1e-8f

// ---------------- device scratch (no allocations allowed) ----------------
__device__ unsigned g_keys[8];          // 0..2: max(q/k/v in), 3: max(attn_out), 4..7: max|Wq/Wk/Wv/Wo|
__device__ unsigned g_spraw[Ss];        // p_attn per-key-column max (raw nonneg float bits)
__device__ float g_sq[Ss], g_sk[Ss], g_sv[Ss];   // per-seq-position int8 scales
__device__ float g_q[Bb*Hh*Ss*DKk];
__device__ float g_k[Bb*Hh*Ss*DKk];
__device__ float g_v[Bb*Hh*Ss*DKk];
__device__ signed char g_qq[Bb*Hh*Ss*DKk];
__device__ signed char g_kq[Bb*Hh*Ss*DKk];
__device__ signed char g_vq[Bb*Hh*Ss*DKk];
__device__ float g_p[Bb*Hh*Ss*Ss];      // p_attn (post-softmax)
__device__ float g_attn[Mm*DMm];        // attention output in [B,S,DM] layout
__device__ unsigned char g_xq[Mm*DMm];  // quantized activations (u8), reused per projection
__device__ signed char   g_wq[DMm*DMm]; // quantized weights (s8), reused per projection

// monotone key for float max via unsigned atomicMax (handles negatives)
__device__ __forceinline__ unsigned fkey(float f) {
    unsigned b = __float_as_uint(f);
    return (b & 0x80000000u) ? ~b : (b | 0x80000000u);
}
__device__ __forceinline__ float funkey(unsigned k) {
    unsigned b = (k & 0x80000000u) ? (k & 0x7fffffffu) : ~k;
    return __uint_as_float(b);
}

// fast exp for x <= 0 (softmax): 2^t with degree-5 poly, rel err ~2.4e-6
__device__ __forceinline__ float fast_exp(float x) {
    float t = x * 1.4426950408889634f;
    t = fmaxf(t, -127.0f);
    float n = rintf(t);
    float f = t - n;
    float p = 1.3333558146428443e-3f;
    p = fmaf(p, f, 9.618129107628477e-3f);
    p = fmaf(p, f, 5.550410866482158e-2f);
    p = fmaf(p, f, 2.402265069591007e-1f);
    p = fmaf(p, f, 6.931471805599453e-1f);
    p = fmaf(p, f, 1.0f);
    float r = __int_as_float(((int)n + 127) << 23);
    return p * r;
}

__device__ __forceinline__ float blockReduceMax(float v) {
    __shared__ float sm[32];
    #pragma unroll
    for (int o = 16; o > 0; o >>= 1) v = fmaxf(v, __shfl_xor_sync(0xffffffffu, v, o));
    int lane = threadIdx.x & 31, w = threadIdx.x >> 5;
    if (lane == 0) sm[w] = v;
    __syncthreads();
    int nw = (blockDim.x + 31) >> 5;
    v = (threadIdx.x < nw) ? sm[threadIdx.x] : -INFINITY;
    if (w == 0) {
        #pragma unroll
        for (int o = 16; o > 0; o >>= 1) v = fmaxf(v, __shfl_xor_sync(0xffffffffu, v, o));
    }
    return v;  // valid in thread 0
}

// ---------------- mma / ldmatrix helpers ----------------
__device__ __forceinline__ void ldsm_x4(unsigned &r0, unsigned &r1, unsigned &r2, unsigned &r3,
                                        const void* p) {
    unsigned a = (unsigned)__cvta_generic_to_shared(p);
    asm volatile("ldmatrix.sync.aligned.m8n8.x4.shared.b16 {%0,%1,%2,%3}, [%4];"
                 : "=r"(r0), "=r"(r1), "=r"(r2), "=r"(r3) : "r"(a));
}
__device__ __forceinline__ void ldsm_x4_t(unsigned &r0, unsigned &r1, unsigned &r2, unsigned &r3,
                                          const void* p) {
    unsigned a = (unsigned)__cvta_generic_to_shared(p);
    asm volatile("ldmatrix.sync.aligned.m8n8.x4.trans.shared.b16 {%0,%1,%2,%3}, [%4];"
                 : "=r"(r0), "=r"(r1), "=r"(r2), "=r"(r3) : "r"(a));
}
__device__ __forceinline__ void mma_u8s8(int* c, const unsigned* a, const unsigned* b) {
    asm volatile("mma.sync.aligned.m16n8k32.row.col.s32.u8.s8.s32 "
                 "{%0,%1,%2,%3}, {%4,%5,%6,%7}, {%8,%9}, {%0,%1,%2,%3};"
                 : "+r"(c[0]), "+r"(c[1]), "+r"(c[2]), "+r"(c[3])
                 : "r"(a[0]), "r"(a[1]), "r"(a[2]), "r"(a[3]), "r"(b[0]), "r"(b[1]));
}
__device__ __forceinline__ void mma_s8s8(int* c, const unsigned* a, const unsigned* b) {
    asm volatile("mma.sync.aligned.m16n8k32.row.col.s32.s8.s8.s32 "
                 "{%0,%1,%2,%3}, {%4,%5,%6,%7}, {%8,%9}, {%0,%1,%2,%3};"
                 : "+r"(c[0]), "+r"(c[1]), "+r"(c[2]), "+r"(c[3])
                 : "r"(a[0]), "r"(a[1]), "r"(a[2]), "r"(a[3]), "r"(b[0]), "r"(b[1]));
}
__device__ __forceinline__ void mma_f16(float* c, const unsigned* a, const unsigned* b) {
    asm volatile("mma.sync.aligned.m16n8k16.row.col.f32.f16.f16.f32 "
                 "{%0,%1,%2,%3}, {%4,%5,%6,%7}, {%8,%9}, {%0,%1,%2,%3};"
                 : "+f"(c[0]), "+f"(c[1]), "+f"(c[2]), "+f"(c[3])
                 : "r"(a[0]), "r"(a[1]), "r"(a[2]), "r"(a[3]), "r"(b[0]), "r"(b[1]));
}

// ---------------- kernels ----------------

__global__ void k_init() {
    int t = threadIdx.x;
    if (t < 8) g_keys[t] = 0u;
    if (t < Ss) g_spraw[t] = 0u;
}

// global max (optionally of |x|) over n4 float4's -> g_keys[slot]; x==nullptr means g_attn
__global__ void k_redmax4(const float4* __restrict__ x, int n4, int slot, int useabs) {
    if (x == nullptr) x = (const float4*)g_attn;
    float m = -INFINITY;
    for (int i = blockIdx.x * blockDim.x + threadIdx.x; i < n4; i += gridDim.x * blockDim.x) {
        float4 v = x[i];
        if (useabs) {
            m = fmaxf(m, fmaxf(fmaxf(fabsf(v.x), fabsf(v.y)), fmaxf(fabsf(v.z), fabsf(v.w))));
        } else {
            m = fmaxf(m, fmaxf(fmaxf(v.x, v.y), fmaxf(v.z, v.w)));
        }
    }
    m = blockReduceMax(m);
    if (threadIdx.x == 0) atomicMax(&g_keys[slot], fkey(m));
}

// quantize activations f32 -> u8 into g_xq (x==nullptr means g_attn)
__global__ void k_quantX(const float4* __restrict__ x, int n4, int slot) {
    if (x == nullptr) x = (const float4*)g_attn;
    float s = fmaxf(funkey(g_keys[slot]), FQ_EPS) / 255.0f;
    uchar4* o = (uchar4*)g_xq;
    for (int i = blockIdx.x * blockDim.x + threadIdx.x; i < n4; i += gridDim.x * blockDim.x) {
        float4 v = x[i];
        uchar4 u;
        u.x = (unsigned char)fminf(fmaxf(rintf(v.x / s), 0.f), 255.f);
        u.y = (unsigned char)fminf(fmaxf(rintf(v.y / s), 0.f), 255.f);
        u.z = (unsigned char)fminf(fmaxf(rintf(v.z / s), 0.f), 255.f);
        u.w = (unsigned char)fminf(fmaxf(rintf(v.w / s), 0.f), 255.f);
        o[i] = u;
    }
}

// quantize weights f32 -> s8 into g_wq
__global__ void k_quantW(const float4* __restrict__ w, int n4, int slot) {
    float s = fmaxf(funkey(g_keys[slot]), FQ_EPS) / 127.0f;
    char4* o = (char4*)g_wq;
    for (int i = blockIdx.x * blockDim.x + threadIdx.x; i < n4; i += gridDim.x * blockDim.x) {
        float4 v = w[i];
        char4 u;
        u.x = (signed char)fminf(fmaxf(rintf(v.x / s), -127.f), 127.f);
        u.y = (signed char)fminf(fmaxf(rintf(v.y / s), -127.f), 127.f);
        u.z = (signed char)fminf(fmaxf(rintf(v.z / s), -127.f), 127.f);
        u.w = (signed char)fminf(fmaxf(rintf(v.w / s), -127.f), 127.f);
        o[i] = u;
    }
}

// int8 tensor-core GEMM: C[m,n] = (sum_d Xq[m,d]*Wq[n,d]) * s_b + round(bias[n]/s_b)*s_b
__global__ __launch_bounds__(256, 2) void k_gemm_i8(const float* __restrict__ bias,
                                                    float* __restrict__ outp,
                                                    int slot_in, int slot_w, int mode) {
    __shared__ unsigned char As[128 * 80];
    __shared__ unsigned char Bs[128 * 80];
    int tid = threadIdx.x, lane = tid & 31, w = tid >> 5;
    int wm = w & 3, wn = w >> 2;           // 4 warps in M, 2 in N
    int bm = blockIdx.y * 128, bn = blockIdx.x * 128;
    int r0 = tid >> 2, q4 = tid & 3;

    int acc[2][8][4] = {};

    int arow_off = (lane & 7) + ((lane >> 3) & 1) * 8;
    int akb = (lane >> 4) * 16;
    int bcol_off = (lane & 7) + (lane >> 4) * 8;
    int bkb = ((lane >> 3) & 1) * 16;

    for (int k0 = 0; k0 < DMm; k0 += 64) {
        int4 xa = *(const int4*)&g_xq[(bm + r0) * DMm + k0 + q4 * 16];
        int4 xb = *(const int4*)&g_xq[(bm + r0 + 64) * DMm + k0 + q4 * 16];
        int4 wa = *(const int4*)&g_wq[(bn + r0) * DMm + k0 + q4 * 16];
        int4 wb = *(const int4*)&g_wq[(bn + r0 + 64) * DMm + k0 + q4 * 16];
        __syncthreads();
        *(int4*)&As[r0 * 80 + q4 * 16] = xa;
        *(int4*)&As[(r0 + 64) * 80 + q4 * 16] = xb;
        *(int4*)&Bs[r0 * 80 + q4 * 16] = wa;
        *(int4*)&Bs[(r0 + 64) * 80 + q4 * 16] = wb;
        __syncthreads();
        #pragma unroll
        for (int ks = 0; ks < 2; ks++) {
            unsigned a[2][4];
            #pragma unroll
            for (int mi = 0; mi < 2; mi++) {
                int row = wm * 32 + mi * 16 + arow_off;
                ldsm_x4(a[mi][0], a[mi][1], a[mi][2], a[mi][3], &As[row * 80 + ks * 32 + akb]);
            }
            unsigned b[8][2];
            #pragma unroll
            for (int pr = 0; pr < 4; pr++) {
                int col = wn * 64 + pr * 16 + bcol_off;
                unsigned t0, t1, t2, t3;
                ldsm_x4(t0, t1, t2, t3, &Bs[col * 80 + ks * 32 + bkb]);
                b[pr * 2][0] = t0; b[pr * 2][1] = t1;
                b[pr * 2 + 1][0] = t2; b[pr * 2 + 1][1] = t3;
            }
            #pragma unroll
            for (int mi = 0; mi < 2; mi++)
                #pragma unroll
                for (int ni = 0; ni < 8; ni++)
                    mma_u8s8(acc[mi][ni], a[mi], b[ni]);
        }
    }

    float s_in = fmaxf(funkey(g_keys[slot_in]), FQ_EPS) / 255.0f;
    float s_w  = fmaxf(funkey(g_keys[slot_w]),  FQ_EPS) / 127.0f;
    float s_b = s_in * s_w;
    int gid = lane >> 2, tg = lane & 3;
    #pragma unroll
    for (int mi = 0; mi < 2; mi++) {
        #pragma unroll
        for (int half = 0; half < 2; half++) {
            int m = bm + wm * 32 + mi * 16 + gid + half * 8;
            int b_ = m >> 7, s_ = m & 127;
            #pragma unroll
            for (int ni = 0; ni < 8; ni++) {
                #pragma unroll
                for (int cc = 0; cc < 2; cc++) {
                    int n = bn + wn * 64 + ni * 8 + tg * 2 + cc;
                    float bq = rintf(bias[n] / s_b) * s_b;
                    float v = (float)acc[mi][ni][half * 2 + cc] * s_b + bq;
                    if (mode < 3) {
                        float* out = (mode == 0) ? g_q : (mode == 1) ? g_k : g_v;
                        int h = n >> 6, dk = n & 63;
                        out[((b_ * Hh + h) * Ss + s_) * DKk + dk] = v;
                    } else {
                        outp[m * DMm + n] = v;
                    }
                }
            }
        }
    }
}

// per-seq-position abs-max scale over (B,H,DK) for g_q/g_k/g_v (sel 0/1/2)
__global__ void k_rowscale(int sel) {
    const float* t = (sel == 0) ? g_q : (sel == 1) ? g_k : g_v;
    float* outp    = (sel == 0) ? g_sq : (sel == 1) ? g_sk : g_sv;
    int s = blockIdx.x;
    float m = 0.f;
    for (int u = threadIdx.x; u < Bb * Hh * DKk; u += blockDim.x) {
        int bh = u >> 6, dk = u & 63;
        m = fmaxf(m, fabsf(t[bh * Ss * DKk + s * DKk + dk]));
    }
    m = blockReduceMax(m);
    if (threadIdx.x == 0) outp[s] = fmaxf(m, FQ_EPS) / 127.0f;
}

// quantize q/k/v (fp32 [bh,s,dk]) -> s8 with per-s scales
__global__ void k_quantqkv() {
    int t = blockIdx.y;
    const float4* src = (t == 0) ? (const float4*)g_q : (t == 1) ? (const float4*)g_k : (const float4*)g_v;
    const float* sc   = (t == 0) ? g_sq : (t == 1) ? g_sk : g_sv;
    char4* dst        = (t == 0) ? (char4*)g_qq : (t == 1) ? (char4*)g_kq : (char4*)g_vq;
    int n4 = Bb * Hh * Ss * DKk / 4;
    for (int i = blockIdx.x * blockDim.x + threadIdx.x; i < n4; i += gridDim.x * blockDim.x) {
        int s = (i >> 4) & 127;
        float sv = sc[s];
        float4 v = src[i];
        char4 o;
        o.x = (signed char)fminf(fmaxf(rintf(v.x / sv), -128.f), 127.f);
        o.y = (signed char)fminf(fmaxf(rintf(v.y / sv), -128.f), 127.f);
        o.z = (signed char)fminf(fmaxf(rintf(v.z / sv), -128.f), 127.f);
        o.w = (signed char)fminf(fmaxf(rintf(v.w / sv), -128.f), 127.f);
        dst[i] = o;
    }
}

// fused scores + softmax + column max: one block per (b,h).
// scores = (qq . kq) * sq[i]*sk[j]/8  (exact s32), mask, softmax rows, p -> g_p,
// per-column p max -> g_spraw.
__global__ __launch_bounds__(256) void k_scores_fused(const int* __restrict__ mask) {
    __shared__ signed char Aq[128 * 80];
    __shared__ signed char Bq[128 * 80];
    __shared__ float sqs[128], sks[128];
    __shared__ float srmax[2][128];
    __shared__ float srsum[2][128];
    __shared__ float sinv[128];
    __shared__ unsigned scol[128];
    int bh = blockIdx.x;
    int b_ = bh >> 4;
    int tid = threadIdx.x, lane = tid & 31, w = tid >> 5;
    int wm = w & 3, wn = w >> 2;

    if (tid < 128) {
        sqs[tid] = g_sq[tid];
        sks[tid] = g_sk[tid];
        scol[tid] = 0u;
    }
    const int4* qsrc = (const int4*)(g_qq + bh * Ss * DKk);
    const int4* ksrc = (const int4*)(g_kq + bh * Ss * DKk);
    #pragma unroll
    for (int part = 0; part < 2; part++) {
        int idx = part * 256 + tid;
        int row = idx >> 2, c16 = idx & 3;
        *(int4*)&Aq[row * 80 + c16 * 16] = qsrc[idx];
        *(int4*)&Bq[row * 80 + c16 * 16] = ksrc[idx];
    }
    __syncthreads();

    int acc[2][8][4] = {};
    int arow_off = (lane & 7) + ((lane >> 3) & 1) * 8;
    int akb = (lane >> 4) * 16;
    int bcol_off = (lane & 7) + (lane >> 4) * 8;
    int bkb = ((lane >> 3) & 1) * 16;
    #pragma unroll
    for (int ks = 0; ks < 2; ks++) {
        unsigned a[2][4];
        #pragma unroll
        for (int mi = 0; mi < 2; mi++) {
            int row = wm * 32 + mi * 16 + arow_off;
            ldsm_x4(a[mi][0], a[mi][1], a[mi][2], a[mi][3], &Aq[row * 80 + ks * 32 + akb]);
        }
        unsigned b[8][2];
        #pragma unroll
        for (int pr = 0; pr < 4; pr++) {
            int col = wn * 64 + pr * 16 + bcol_off;
            unsigned t0, t1, t2, t3;
            ldsm_x4(t0, t1, t2, t3, &Bq[col * 80 + ks * 32 + bkb]);
            b[pr * 2][0] = t0; b[pr * 2][1] = t1;
            b[pr * 2 + 1][0] = t2; b[pr * 2 + 1][1] = t3;
        }
        #pragma unroll
        for (int mi = 0; mi < 2; mi++)
            #pragma unroll
            for (int ni = 0; ni < 8; ni++)
                mma_s8s8(acc[mi][ni], a[mi], b[ni]);
    }

    int gid = lane >> 2, tg = lane & 3;
    const int* mrow = mask + b_ * Ss * Ss;
    float rmax[4] = {-INFINITY, -INFINITY, -INFINITY, -INFINITY};
    #pragma unroll
    for (int mi = 0; mi < 2; mi++) {
        #pragma unroll
        for (int rh = 0; rh < 2; rh++) {
            int i = wm * 32 + mi * 16 + gid + rh * 8;
            float sqi = sqs[i] * 0.125f;
            #pragma unroll
            for (int ni = 0; ni < 8; ni++) {
                #pragma unroll
                for (int cc = 0; cc < 2; cc++) {
                    int j = wn * 64 + ni * 8 + tg * 2 + cc;
                    float v = (float)acc[mi][ni][rh * 2 + cc] * (sqi * sks[j]);
                    if (mrow[i * Ss + j] == 0) v = -1e9f;
                    acc[mi][ni][rh * 2 + cc] = __float_as_int(v);
                    rmax[mi * 2 + rh] = fmaxf(rmax[mi * 2 + rh], v);
                }
            }
        }
    }
    #pragma unroll
    for (int r = 0; r < 4; r++) {
        rmax[r] = fmaxf(rmax[r], __shfl_xor_sync(0xffffffffu, rmax[r], 1));
        rmax[r] = fmaxf(rmax[r], __shfl_xor_sync(0xffffffffu, rmax[r], 2));
    }
    if (tg == 0) {
        #pragma unroll
        for (int mi = 0; mi < 2; mi++)
            #pragma unroll
            for (int rh = 0; rh < 2; rh++)
                srmax[wn][wm * 32 + mi * 16 + gid + rh * 8] = rmax[mi * 2 + rh];
    }
    __syncthreads();

    float rsum[4] = {0.f, 0.f, 0.f, 0.f};
    #pragma unroll
    for (int mi = 0; mi < 2; mi++) {
        #pragma unroll
        for (int rh = 0; rh < 2; rh++) {
            int i = wm * 32 + mi * 16 + gid + rh * 8;
            float rm = fmaxf(srmax[0][i], srmax[1][i]);
            #pragma unroll
            for (int ni = 0; ni < 8; ni++) {
                #pragma unroll
                for (int cc = 0; cc < 2; cc++) {
                    float v = __int_as_float(acc[mi][ni][rh * 2 + cc]);
                    float e = fast_exp(v - rm);
                    acc[mi][ni][rh * 2 + cc] = __float_as_int(e);
                    rsum[mi * 2 + rh] += e;
                }
            }
        }
    }
    #pragma unroll
    for (int r = 0; r < 4; r++) {
        rsum[r] += __shfl_xor_sync(0xffffffffu, rsum[r], 1);
        rsum[r] += __shfl_xor_sync(0xffffffffu, rsum[r], 2);
    }
    if (tg == 0) {
        #pragma unroll
        for (int mi = 0; mi < 2; mi++)
            #pragma unroll
            for (int rh = 0; rh < 2; rh++)
                srsum[wn][wm * 32 + mi * 16 + gid + rh * 8] = rsum[mi * 2 + rh];
    }
    __syncthreads();
    if (tid < 128) sinv[tid] = 1.0f / (srsum[0][tid] + srsum[1][tid]);
    __syncthreads();

    float cmax[16];
    #pragma unroll
    for (int c = 0; c < 16; c++) cmax[c] = 0.f;
    float* pout = g_p + bh * Ss * Ss;
    #pragma unroll
    for (int mi = 0; mi < 2; mi++) {
        #pragma unroll
        for (int rh = 0; rh < 2; rh++) {
            int i = wm * 32 + mi * 16 + gid + rh * 8;
            float iv = sinv[i];
            #pragma unroll
            for (int ni = 0; ni < 8; ni++) {
                float p0 = __int_as_float(acc[mi][ni][rh * 2 + 0]) * iv;
                float p1 = __int_as_float(acc[mi][ni][rh * 2 + 1]) * iv;
                cmax[ni * 2 + 0] = fmaxf(cmax[ni * 2 + 0], p0);
                cmax[ni * 2 + 1] = fmaxf(cmax[ni * 2 + 1], p1);
                *(float2*)&pout[i * Ss + wn * 64 + ni * 8 + tg * 2] = make_float2(p0, p1);
            }
        }
    }
    #pragma unroll
    for (int c = 0; c < 16; c++) {
        cmax[c] = fmaxf(cmax[c], __shfl_xor_sync(0xffffffffu, cmax[c], 4));
        cmax[c] = fmaxf(cmax[c], __shfl_xor_sync(0xffffffffu, cmax[c], 8));
        cmax[c] = fmaxf(cmax[c], __shfl_xor_sync(0xffffffffu, cmax[c], 16));
    }
    if (gid == 0) {
        #pragma unroll
        for (int ni = 0; ni < 8; ni++) {
            #pragma unroll
            for (int cc = 0; cc < 2; cc++)
                atomicMax(&scol[wn * 64 + ni * 8 + tg * 2 + cc], __float_as_uint(cmax[ni * 2 + cc]));
        }
    }
    __syncthreads();
    if (tid < 128) atomicMax(&g_spraw[tid], scol[tid]);
}

// attn: x[i,dk] = sum_j pq[i,j] * (sp[j]*sv[j]*vq[j,dk])  via fp16 MMA, B split hi/lo.
// one block per (b,h); M=128 N=64 K=128 (two 64-j halves).
__global__ __launch_bounds__(256) void k_attn_mma() {
    __shared__ half As[128 * 72];
    __shared__ half Bhh[64 * 72];
    __shared__ half Bll[64 * 72];
    __shared__ float ssp[128];   // sp[j]
    __shared__ float scc[128];   // sp[j]*sv[j]
    int bh = blockIdx.x;
    int b_ = bh >> 4, h_ = bh & 15;
    int tid = threadIdx.x, lane = tid & 31, w = tid >> 5;
    int wm = w & 3, wn = w >> 2;

    if (tid < 128) {
        float sp = fmaxf(__uint_as_float(g_spraw[tid]), FQ_EPS) / 127.0f;
        ssp[tid] = sp;
        scc[tid] = sp * g_sv[tid];
    }
    __syncthreads();

    float acc[2][4][4] = {};
    const float* P = g_p + bh * Ss * Ss;
    const char4* V = (const char4*)(g_vq + bh * Ss * DKk);

    for (int kh = 0; kh < 2; kh++) {
        // A: p[i, kh*64 + jq], quantize to pq (exact in fp16)
        #pragma unroll
        for (int t = 0; t < 8; t++) {
            int idx = t * 256 + tid;
            int i = idx >> 4;
            int jq = (idx & 15) * 4;
            int jg = kh * 64 + jq;
            float4 pv = *(const float4*)&P[i * Ss + jg];
            half h0 = __float2half_rn(fminf(fmaxf(rintf(pv.x / ssp[jg + 0]), -128.f), 127.f));
            half h1 = __float2half_rn(fminf(fmaxf(rintf(pv.y / ssp[jg + 1]), -128.f), 127.f));
            half h2 = __float2half_rn(fminf(fmaxf(rintf(pv.z / ssp[jg + 2]), -128.f), 127.f));
            half h3 = __float2half_rn(fminf(fmaxf(rintf(pv.w / ssp[jg + 3]), -128.f), 127.f));
            half2* dst = (half2*)&As[i * 72 + jq];
            dst[0] = __halves2half2(h0, h1);
            dst[1] = __halves2half2(h2, h3);
        }
        // B: vq[kh*64 + j, dk] * scc -> hi/lo fp16
        #pragma unroll
        for (int t = 0; t < 4; t++) {
            int idx = t * 256 + tid;
            int j = idx >> 4;
            int dk4 = (idx & 15) * 4;
            int jg = kh * 64 + j;
            char4 vv = V[jg * 16 + (idx & 15)];
            float c = scc[jg];
            float f0 = c * (float)vv.x, f1 = c * (float)vv.y;
            float f2 = c * (float)vv.z, f3 = c * (float)vv.w;
            half b0 = __float2half_rn(f0), b1 = __float2half_rn(f1);
            half b2 = __float2half_rn(f2), b3 = __float2half_rn(f3);
            half l0 = __float2half_rn(f0 - __half2float(b0));
            half l1 = __float2half_rn(f1 - __half2float(b1));
            half l2 = __float2half_rn(f2 - __half2float(b2));
            half l3 = __float2half_rn(f3 - __half2float(b3));
            half2* dh = (half2*)&Bhh[j * 72 + dk4];
            dh[0] = __halves2half2(b0, b1); dh[1] = __halves2half2(b2, b3);
            half2* dl = (half2*)&Bll[j * 72 + dk4];
            dl[0] = __halves2half2(l0, l1); dl[1] = __halves2half2(l2, l3);
        }
        __syncthreads();

        #pragma unroll
        for (int ks = 0; ks < 4; ks++) {
            unsigned a[2][4];
            #pragma unroll
            for (int mf = 0; mf < 2; mf++) {
                int row = wm * 32 + mf * 16 + (lane & 15);
                ldsm_x4(a[mf][0], a[mf][1], a[mf][2], a[mf][3],
                        &As[row * 72 + ks * 16 + (lane >> 4) * 8]);
            }
            unsigned bh2[4][2], bl2[4][2];
            #pragma unroll
            for (int nh = 0; nh < 2; nh++) {
                int brow = ks * 16 + (lane & 15);
                int bcol = wn * 32 + nh * 16 + (lane >> 4) * 8;
                unsigned t0, t1, t2, t3;
                ldsm_x4_t(t0, t1, t2, t3, &Bhh[brow * 72 + bcol]);
                bh2[nh * 2][0] = t0; bh2[nh * 2][1] = t1;
                bh2[nh * 2 + 1][0] = t2; bh2[nh * 2 + 1][1] = t3;
                ldsm_x4_t(t0, t1, t2, t3, &Bll[brow * 72 + bcol]);
                bl2[nh * 2][0] = t0; bl2[nh * 2][1] = t1;
                bl2[nh * 2 + 1][0] = t2; bl2[nh * 2 + 1][1] = t3;
            }
            #pragma unroll
            for (int mf = 0; mf < 2; mf++) {
                #pragma unroll
                for (int nf = 0; nf < 4; nf++) {
                    mma_f16(acc[mf][nf], a[mf], bh2[nf]);
                    mma_f16(acc[mf][nf], a[mf], bl2[nf]);
                }
            }
        }
        __syncthreads();
    }

    int gid = lane >> 2, tg = lane & 3;
    #pragma unroll
    for (int mf = 0; mf < 2; mf++) {
        #pragma unroll
        for (int nf = 0; nf < 4; nf++) {
            #pragma unroll
            for (int rh = 0; rh < 2; rh++) {
                int i = wm * 32 + mf * 16 + gid + rh * 8;
                int dk = wn * 32 + nf * 8 + tg * 2;
                *(float2*)&g_attn[(b_ * Ss + i) * DMm + h_ * DKk + dk] =
                    make_float2(acc[mf][nf][rh * 2 + 0], acc[mf][nf][rh * 2 + 1]);
            }
        }
    }
}

extern "C" void kernel_launch(void* const* d_in, const int* in_sizes, int n_in,
                              void* d_out, int out_size) {
    const float* query = (const float*)d_in[0];
    const float* key   = (const float*)d_in[1];
    const float* value = (const float*)d_in[2];
    const int*   mask  = (const int*)d_in[3];
    const float* Wq = (const float*)d_in[4];
    const float* bq = (const float*)d_in[5];
    const float* Wk = (const float*)d_in[6];
    const float* bk = (const float*)d_in[7];
    const float* Wv = (const float*)d_in[8];
    const float* bv = (const float*)d_in[9];
    const float* Wo = (const float*)d_in[10];
    const float* bo = (const float*)d_in[11];
    float* out = (float*)d_out;

    const int NX4 = Mm * DMm / 4;
    const int NW4 = DMm * DMm / 4;

    k_init<<<1, 128>>>();

    k_redmax4<<<1024, 256>>>((const float4*)query, NX4, 0, 0);
    k_redmax4<<<1024, 256>>>((const float4*)key,   NX4, 1, 0);
    k_redmax4<<<1024, 256>>>((const float4*)value, NX4, 2, 0);
    k_redmax4<<<512, 256>>>((const float4*)Wq, NW4, 4, 1);
    k_redmax4<<<512, 256>>>((const float4*)Wk, NW4, 5, 1);
    k_redmax4<<<512, 256>>>((const float4*)Wv, NW4, 6, 1);
    k_redmax4<<<512, 256>>>((const float4*)Wo, NW4, 7, 1);

    dim3 gg(DMm / 128, Mm / 128);
    k_quantX<<<2048, 256>>>((const float4*)query, NX4, 0);
    k_quantW<<<1024, 256>>>((const float4*)Wq, NW4, 4);
    k_gemm_i8<<<gg, 256>>>(bq, nullptr, 0, 4, 0);
    k_quantX<<<2048, 256>>>((const float4*)key, NX4, 1);
    k_quantW<<<1024, 256>>>((const float4*)Wk, NW4, 5);
    k_gemm_i8<<<gg, 256>>>(bk, nullptr, 1, 5, 1);
    k_quantX<<<2048, 256>>>((const float4*)value, NX4, 2);
    k_quantW<<<1024, 256>>>((const float4*)Wv, NW4, 6);
    k_gemm_i8<<<gg, 256>>>(bv, nullptr, 2, 6, 2);

    k_rowscale<<<Ss, 256>>>(0);
    k_rowscale<<<Ss, 256>>>(1);
    k_rowscale<<<Ss, 256>>>(2);
    k_quantqkv<<<dim3(1024, 3), 256>>>();

    k_scores_fused<<<Bb * Hh, 256>>>(mask);
    k_attn_mma<<<Bb * Hh, 256>>>();

    k_redmax4<<<1024, 256>>>(nullptr, NX4, 3, 0);
    k_quantX<<<2048, 256>>>(nullptr, NX4, 3);
    k_quantW<<<1024, 256>>>((const float4*)Wo, NW4, 7);
    k_gemm_i8<<<gg, 256>>>(bo, out, 3, 7, 3);
}